// round 14
// baseline (speedup 1.0000x reference)
#include <cuda_runtime.h>
#include <cuda_bf16.h>
#include <math.h>
#include <stdint.h>

// ---------------------------------------------------------------------------
// Problem constants
// ---------------------------------------------------------------------------
#define N_CLASS   128
#define N_SUPPORT 32
#define N_QUERY   128
#define IN_DIM    2048
#define Z_DIM     1024
#define KCLUST    2

#define NS_ROWS (N_CLASS * N_SUPPORT)   // 4096
#define NQ_ROWS (N_CLASS * N_QUERY)    // 16384
#define NZ_ROWS (NS_ROWS + NQ_ROWS)    // 20480
#define N_PROTO (N_CLASS * KCLUST)     // 256

// ---------------------------------------------------------------------------
// Scratch (device globals; no allocation allowed)
// ---------------------------------------------------------------------------
__device__ float g_z[(size_t)NZ_ROWS * Z_DIM];          // fp32 z (support region used)
__device__ float g_protos[(size_t)N_PROTO * Z_DIM];
__device__ float g_proto_sq[N_PROTO];
__device__ float g_qnorm[NQ_ROWS];
__device__ double g_qpart[(size_t)NQ_ROWS * 8];         // per-coltile norm partials
__device__ float g_dists[(size_t)NQ_ROWS * N_CLASS];
__device__ float g_lpart[NQ_ROWS];
__device__ float g_apart[NQ_ROWS];
__device__ int g_adec[NS_ROWS];                         // per-support decision

// bf16 splits
__device__ __nv_bfloat16 g_A0[(size_t)NZ_ROWS * IN_DIM];
__device__ __nv_bfloat16 g_A1[(size_t)NZ_ROWS * IN_DIM];
__device__ __nv_bfloat16 g_A2[(size_t)NZ_ROWS * IN_DIM];
__device__ __nv_bfloat16 g_WT0[(size_t)Z_DIM * IN_DIM];
__device__ __nv_bfloat16 g_WT1[(size_t)Z_DIM * IN_DIM];
__device__ __nv_bfloat16 g_WT2[(size_t)Z_DIM * IN_DIM];
__device__ __nv_bfloat16 g_Zq0[(size_t)NQ_ROWS * Z_DIM];
__device__ __nv_bfloat16 g_Zq1[(size_t)NQ_ROWS * Z_DIM];
__device__ __nv_bfloat16 g_Zq2[(size_t)NQ_ROWS * Z_DIM];
__device__ __nv_bfloat16 g_P0[(size_t)N_PROTO * Z_DIM];
__device__ __nv_bfloat16 g_P1[(size_t)N_PROTO * Z_DIM];
__device__ __nv_bfloat16 g_P2[(size_t)N_PROTO * Z_DIM];

// ---------------------------------------------------------------------------
// Baseline-PTX helpers (mma.sync / ldmatrix / cp.async)
// ---------------------------------------------------------------------------
__device__ __forceinline__ uint32_t smem_u32(const void* p) {
    uint32_t a;
    asm("{ .reg .u64 t; cvta.to.shared.u64 t, %1; cvt.u32.u64 %0, t; }"
        : "=r"(a) : "l"(p));
    return a;
}

#define CP_ASYNC16(smem_addr, gptr) \
    asm volatile("cp.async.cg.shared.global [%0], [%1], 16;" \
                 :: "r"(smem_addr), "l"(gptr))
#define CP_COMMIT() asm volatile("cp.async.commit_group;" ::: "memory")
#define CP_WAIT1()  asm volatile("cp.async.wait_group 1;" ::: "memory")

#define LDSM_X4(r0, r1, r2, r3, addr) \
    asm volatile("ldmatrix.sync.aligned.m8n8.x4.shared.b16 {%0,%1,%2,%3}, [%4];" \
                 : "=r"(r0), "=r"(r1), "=r"(r2), "=r"(r3) : "r"(addr))

#define MMA_BF16(d0, d1, d2, d3, a0, a1, a2, a3, b0, b1) \
    asm volatile( \
        "mma.sync.aligned.m16n8k16.row.col.f32.bf16.bf16.f32 " \
        "{%0,%1,%2,%3}, {%4,%5,%6,%7}, {%8,%9}, {%0,%1,%2,%3};" \
        : "+f"(d0), "+f"(d1), "+f"(d2), "+f"(d3) \
        : "r"(a0), "r"(a1), "r"(a2), "r"(a3), "r"(b0), "r"(b1))

// Swizzled smem tile: logical [128 rows][64 B]; rows paired into 128B lines,
// 16B chunk cc = ((row&1)<<2)|c XOR-swizzled by (row>>1)&7.
__device__ __forceinline__ uint32_t tile_off(int row, int c) {
    int cc = ((row & 1) << 2) | c;
    int p  = cc ^ ((row >> 1) & 7);
    return (uint32_t)((row >> 1) * 128 + p * 16);
}

// ---------------------------------------------------------------------------
// bf16 3-way split helpers
// ---------------------------------------------------------------------------
__device__ __forceinline__ void split3(float x, unsigned short& s0,
                                       unsigned short& s1, unsigned short& s2)
{
    __nv_bfloat16 h0 = __float2bfloat16_rn(x);
    float r = x - __bfloat162float(h0);
    __nv_bfloat16 h1 = __float2bfloat16_rn(r);
    float r2 = r - __bfloat162float(h1);
    __nv_bfloat16 h2 = __float2bfloat16_rn(r2);
    s0 = __bfloat16_as_ushort(h0);
    s1 = __bfloat16_as_ushort(h1);
    s2 = __bfloat16_as_ushort(h2);
}

__device__ __forceinline__ void split4v(const float4& v, ushort4& o0,
                                        ushort4& o1, ushort4& o2)
{
    split3(v.x, o0.x, o1.x, o2.x);
    split3(v.y, o0.y, o1.y, o2.y);
    split3(v.z, o0.z, o1.z, o2.z);
    split3(v.w, o0.w, o1.w, o2.w);
}

// Merged split of A = [xs; xq]: 8 elems per thread, single launch.
__global__ __launch_bounds__(256) void split_ab_kernel(
    const float* __restrict__ xs, const float* __restrict__ xq,
    __nv_bfloat16* __restrict__ d0, __nv_bfloat16* __restrict__ d1,
    __nv_bfloat16* __restrict__ d2)
{
    const int NXS = NS_ROWS * IN_DIM;
    size_t i = ((size_t)blockIdx.x * 256 + threadIdx.x) * 8;
    const float* src = (i < (size_t)NXS) ? (xs + i) : (xq + (i - NXS));
    float4 va = *(const float4*)(src);
    float4 vb = *(const float4*)(src + 4);
    ushort4 a0, a1, a2, b0, b1, b2;
    split4v(va, a0, a1, a2);
    split4v(vb, b0, b1, b2);
    *(ushort4*)(d0 + i) = a0;
    *(ushort4*)(d0 + i + 4) = b0;
    *(ushort4*)(d1 + i) = a1;
    *(ushort4*)(d1 + i + 4) = b1;
    *(ushort4*)(d2 + i) = a2;
    *(ushort4*)(d2 + i + 4) = b2;
}

// Transpose + split W [2048 x 1024] -> WT splits [1024 x 2048].
__global__ __launch_bounds__(256) void split_wt_kernel(
    const float* __restrict__ W,
    __nv_bfloat16* __restrict__ t0, __nv_bfloat16* __restrict__ t1,
    __nv_bfloat16* __restrict__ t2)
{
    __shared__ float tile[32][33];
    int n0 = blockIdx.x * 32;
    int k0 = blockIdx.y * 32;
    int tx = threadIdx.x & 31;
    int ty0 = threadIdx.x >> 5;
    #pragma unroll
    for (int j = 0; j < 4; j++) {
        int ty = ty0 + j * 8;
        tile[ty][tx] = W[(size_t)(k0 + ty) * Z_DIM + n0 + tx];
    }
    __syncthreads();
    #pragma unroll
    for (int j = 0; j < 4; j++) {
        int ty = ty0 + j * 8;
        float x = tile[tx][ty];
        unsigned short s0, s1, s2;
        split3(x, s0, s1, s2);
        size_t o = (size_t)(n0 + ty) * IN_DIM + k0 + tx;
        t0[o] = __ushort_as_bfloat16(s0);
        t1[o] = __ushort_as_bfloat16(s1);
        t2[o] = __ushort_as_bfloat16(s2);
    }
}

// ---------------------------------------------------------------------------
// Unified bf16x6 split GEMM on HMMA, fp32 accumulate.
// CTA 128x128, BK=32, 2-stage cp.async pipeline (R9-proven structure:
// issue next -> commit -> wait_group 1 -> sync). 8 warps (2x4), warp 64x32.
// EPI=1: protonet dist epilogue.
// EPI=2: projection epilogue — support rows: plain fp32 store; query rows:
//        bf16 triple split + fp64 partial row norms (no fp32 store).
// ---------------------------------------------------------------------------
#define GT_TILE  8192                 // one split-tile: 128 rows x 64 B
#define GT_STAGE (6 * GT_TILE)        // 48 KB
#define GT_SMEM  (2 * GT_STAGE)       // 96 KB

template<int K_TOTAL, int EPI>
__global__ __launch_bounds__(256, 2) void gemm6_kernel(
    const __nv_bfloat16* __restrict__ A0, const __nv_bfloat16* __restrict__ A1,
    const __nv_bfloat16* __restrict__ A2,
    const __nv_bfloat16* __restrict__ B0, const __nv_bfloat16* __restrict__ B1,
    const __nv_bfloat16* __restrict__ B2,
    float* __restrict__ out,
    const float* __restrict__ qn, const float* __restrict__ pn,
    __nv_bfloat16* __restrict__ Q0, __nv_bfloat16* __restrict__ Q1,
    __nv_bfloat16* __restrict__ Q2, double* __restrict__ qpart)
{
    extern __shared__ char smem[];
    const uint32_t sb = smem_u32(smem);
    const int tid  = threadIdx.x;
    const int wid  = tid >> 5;
    const int lane = tid & 31;
    const int n0 = blockIdx.x * 128;
    const int m0 = blockIdx.y * 128;

    const int wm = wid & 1;
    const int wn = wid >> 1;
    const int mbase = wm * 64;
    const int nbase = wn * 32;

    const __nv_bfloat16* srcs[6];
    srcs[0] = A0 + (size_t)m0 * K_TOTAL;
    srcs[1] = A1 + (size_t)m0 * K_TOTAL;
    srcs[2] = A2 + (size_t)m0 * K_TOTAL;
    srcs[3] = B0 + (size_t)n0 * K_TOTAL;
    srcs[4] = B1 + (size_t)n0 * K_TOTAL;
    srcs[5] = B2 + (size_t)n0 * K_TOTAL;

    const int ldrow0 = tid >> 2;
    const int ldrow1 = (tid + 256) >> 2;
    const int ldc    = tid & 3;
    const uint32_t soff0 = tile_off(ldrow0, ldc);
    const uint32_t soff1 = tile_off(ldrow1, ldc);

    float acc[64];
    #pragma unroll
    for (int i = 0; i < 64; i++) acc[i] = 0.0f;

    // prologue: stage 0 <- chunk 0
    #pragma unroll
    for (int t = 0; t < 6; t++) {
        CP_ASYNC16(sb + t * GT_TILE + soff0,
                   srcs[t] + (size_t)ldrow0 * K_TOTAL + ldc * 8);
        CP_ASYNC16(sb + t * GT_TILE + soff1,
                   srcs[t] + (size_t)ldrow1 * K_TOTAL + ldc * 8);
    }
    CP_COMMIT();

    const int NCHUNK = K_TOTAL / 32;
    for (int chunk = 0; chunk < NCHUNK; chunk++) {
        // issue next chunk into the other stage (R9-proven ordering)
        if (chunk + 1 < NCHUNK) {
            uint32_t st = sb + ((chunk + 1) & 1) * GT_STAGE;
            size_t kn = (size_t)(chunk + 1) * 32;
            #pragma unroll
            for (int t = 0; t < 6; t++) {
                CP_ASYNC16(st + t * GT_TILE + soff0,
                           srcs[t] + (size_t)ldrow0 * K_TOTAL + kn + ldc * 8);
                CP_ASYNC16(st + t * GT_TILE + soff1,
                           srcs[t] + (size_t)ldrow1 * K_TOTAL + kn + ldc * 8);
            }
        }
        CP_COMMIT();
        CP_WAIT1();
        __syncthreads();

        uint32_t st = sb + (chunk & 1) * GT_STAGE;
        #pragma unroll
        for (int ks = 0; ks < 2; ks++) {
            uint32_t bfr[3][2][4];
            #pragma unroll
            for (int bj = 0; bj < 3; bj++) {
                #pragma unroll
                for (int q = 0; q < 2; q++) {
                    uint32_t off = tile_off(
                        nbase + (2 * q + (lane >> 4)) * 8 + (lane & 7),
                        ks * 2 + ((lane >> 3) & 1));
                    LDSM_X4(bfr[bj][q][0], bfr[bj][q][1],
                            bfr[bj][q][2], bfr[bj][q][3],
                            st + (3 + bj) * GT_TILE + off);
                }
            }
            #pragma unroll
            for (int ai = 0; ai < 3; ai++) {
                uint32_t af[4][4];
                #pragma unroll
                for (int mt = 0; mt < 4; mt++) {
                    uint32_t off = tile_off(mbase + mt * 16 + (lane & 15),
                                            ks * 2 + (lane >> 4));
                    LDSM_X4(af[mt][0], af[mt][1], af[mt][2], af[mt][3],
                            st + ai * GT_TILE + off);
                }
                #pragma unroll
                for (int bj = 0; bj < 3; bj++) {
                    if (ai + bj > 2) continue;
                    #pragma unroll
                    for (int mt = 0; mt < 4; mt++) {
                        #pragma unroll
                        for (int nt = 0; nt < 4; nt++) {
                            float* d = &acc[(mt * 4 + nt) * 4];
                            int q = nt >> 1, h = (nt & 1) * 2;
                            MMA_BF16(d[0], d[1], d[2], d[3],
                                     af[mt][0], af[mt][1], af[mt][2], af[mt][3],
                                     bfr[bj][q][h], bfr[bj][q][h + 1]);
                        }
                    }
                }
            }
        }
        __syncthreads();
    }

    if (EPI == 2) {
        if (m0 < NS_ROWS) {
            // support rows: plain fp32 store (feeds centroid path)
            #pragma unroll
            for (int mt = 0; mt < 4; mt++) {
                #pragma unroll
                for (int nt = 0; nt < 4; nt++) {
                    const float* d = &acc[(mt * 4 + nt) * 4];
                    int r0 = m0 + mbase + mt * 16 + (lane >> 2);
                    int cc = n0 + nbase + nt * 8 + (lane & 3) * 2;
                    *(float2*)(out + (size_t)r0 * Z_DIM + cc) =
                        make_float2(d[0], d[1]);
                    *(float2*)(out + (size_t)(r0 + 8) * Z_DIM + cc) =
                        make_float2(d[2], d[3]);
                }
            }
        } else {
            // query rows: bf16 triple split + fp64 partial norms, no fp32 z
            double* dpart = (double*)smem;   // [128 rows][4 wn]
            const unsigned fm = 0xffffffffu;
            #pragma unroll
            for (int mt = 0; mt < 4; mt++) {
                double rs0 = 0.0, rs1 = 0.0;
                int rl0 = mbase + mt * 16 + (lane >> 2);  // local row
                int q0r = m0 - NS_ROWS + rl0;
                #pragma unroll
                for (int nt = 0; nt < 4; nt++) {
                    const float* d = &acc[(mt * 4 + nt) * 4];
                    int cc = n0 + nbase + nt * 8 + (lane & 3) * 2;
                    unsigned short a0, b0, c0, a1, b1, c1;
                    split3(d[0], a0, b0, c0);
                    split3(d[1], a1, b1, c1);
                    *(ushort2*)((unsigned short*)Q0 + (size_t)q0r * Z_DIM + cc)
                        = make_ushort2(a0, a1);
                    *(ushort2*)((unsigned short*)Q1 + (size_t)q0r * Z_DIM + cc)
                        = make_ushort2(b0, b1);
                    *(ushort2*)((unsigned short*)Q2 + (size_t)q0r * Z_DIM + cc)
                        = make_ushort2(c0, c1);
                    rs0 += (double)d[0] * d[0] + (double)d[1] * d[1];
                    unsigned short a2, b2, c2, a3, b3, c3;
                    split3(d[2], a2, b2, c2);
                    split3(d[3], a3, b3, c3);
                    *(ushort2*)((unsigned short*)Q0 + (size_t)(q0r + 8) * Z_DIM + cc)
                        = make_ushort2(a2, a3);
                    *(ushort2*)((unsigned short*)Q1 + (size_t)(q0r + 8) * Z_DIM + cc)
                        = make_ushort2(b2, b3);
                    *(ushort2*)((unsigned short*)Q2 + (size_t)(q0r + 8) * Z_DIM + cc)
                        = make_ushort2(c2, c3);
                    rs1 += (double)d[2] * d[2] + (double)d[3] * d[3];
                }
                // reduce over the 4 lanes sharing each row
                rs0 += __shfl_down_sync(fm, rs0, 2);
                rs0 += __shfl_down_sync(fm, rs0, 1);
                rs1 += __shfl_down_sync(fm, rs1, 2);
                rs1 += __shfl_down_sync(fm, rs1, 1);
                if ((lane & 3) == 0) {
                    dpart[rl0 * 4 + wn]       = rs0;
                    dpart[(rl0 + 8) * 4 + wn] = rs1;
                }
            }
            __syncthreads();
            if (tid < 128) {
                double s = dpart[tid * 4 + 0] + dpart[tid * 4 + 1]
                         + dpart[tid * 4 + 2] + dpart[tid * 4 + 3];
                int q = m0 - NS_ROWS + tid;
                qpart[(size_t)q * 8 + blockIdx.x] = s;
            }
        }
    } else {
        // EPI == 1: protonet distance epilogue
        #pragma unroll
        for (int mt = 0; mt < 4; mt++) {
            int r0 = m0 + mbase + mt * 16 + (lane >> 2);
            float qv0 = qn[r0];
            float qv1 = qn[r0 + 8];
            #pragma unroll
            for (int nt = 0; nt < 4; nt++) {
                const float* d = &acc[(mt * 4 + nt) * 4];
                int cc = n0 + nbase + nt * 8 + (lane & 3) * 2;
                float p0 = pn[cc], p1 = pn[cc + 1];
                int cls = cc >> 1;
                float e0 = __fadd_rn(__fadd_rn(qv0, p0),
                                     -__fmul_rn(2.0f, d[0]));
                float e1 = __fadd_rn(__fadd_rn(qv0, p1),
                                     -__fmul_rn(2.0f, d[1]));
                out[(size_t)r0 * N_CLASS + cls] =
                    fminf(fmaxf(e0, 0.0f), fmaxf(e1, 0.0f));
                float e2 = __fadd_rn(__fadd_rn(qv1, p0),
                                     -__fmul_rn(2.0f, d[2]));
                float e3 = __fadd_rn(__fadd_rn(qv1, p1),
                                     -__fmul_rn(2.0f, d[3]));
                out[(size_t)(r0 + 8) * N_CLASS + cls] =
                    fminf(fmaxf(e2, 0.0f), fmaxf(e3, 0.0f));
            }
        }
    }
}

// ---------------------------------------------------------------------------
// Fused post-GEMM1 kernel: blocks [0,64) finalize query norms (fixed-order
// fp64 sum of 8 column-tile partials); blocks [64, 64+4096) compute one
// support row's assignment distance PER BLOCK (256 threads x 1 float4 each),
// fixed-order warp-shfl + smem tree reduce. High block count hides latency.
// ---------------------------------------------------------------------------
__global__ __launch_bounds__(256) void post_gemm1_kernel(
    const double* __restrict__ qpart, float* __restrict__ qn,
    const float* __restrict__ z, int* __restrict__ adec)
{
    if (blockIdx.x < 64) {
        int q = blockIdx.x * 256 + threadIdx.x;
        double s = 0.0;
        #pragma unroll
        for (int t = 0; t < 8; t++) s += qpart[(size_t)q * 8 + t];
        qn[q] = (float)s;
        return;
    }
    int b = blockIdx.x - 64;      // 0..4095 (one per support row)
    int c = b >> 5;               // class
    int s = b & 31;               // support
    int tid = threadIdx.x;
    int lane = tid & 31;
    int wid = tid >> 5;

    const float* zs = z + (size_t)c * N_SUPPORT * Z_DIM;
    const float* zr = zs + (size_t)s * Z_DIM;
    int d = tid * 4;
    float4 v  = *(const float4*)(zr + d);
    float4 i0 = *(const float4*)(zs + d);
    float4 i1 = *(const float4*)(zs + Z_DIM + d);

    double ax = (double)v.x - (double)i0.x;
    double ay = (double)v.y - (double)i0.y;
    double az = (double)v.z - (double)i0.z;
    double aw = (double)v.w - (double)i0.w;
    double d0 = fma(aw, aw, fma(az, az, fma(ay, ay, ax * ax)));
    double bx = (double)v.x - (double)i1.x;
    double by = (double)v.y - (double)i1.y;
    double bz = (double)v.z - (double)i1.z;
    double bw = (double)v.w - (double)i1.w;
    double d1 = fma(bw, bw, fma(bz, bz, fma(by, by, bx * bx)));

    #pragma unroll
    for (int o = 16; o > 0; o >>= 1) {
        d0 += __shfl_down_sync(0xffffffffu, d0, o);
        d1 += __shfl_down_sync(0xffffffffu, d1, o);
    }
    __shared__ double r0[8], r1[8];
    if (lane == 0) { r0[wid] = d0; r1[wid] = d1; }
    __syncthreads();
    if (tid == 0) {
        double t0 = ((r0[0] + r0[1]) + (r0[2] + r0[3]))
                  + ((r0[4] + r0[5]) + (r0[6] + r0[7]));
        double t1 = ((r1[0] + r1[1]) + (r1[2] + r1[3]))
                  + ((r1[4] + r1[5]) + (r1[6] + r1[7]));
        adec[c * N_SUPPORT + s] = (t1 < t0) ? 1 : 0;
    }
}

// ---------------------------------------------------------------------------
// Centroid sums: grid 2048 = (class, 64-dim slice). Threads = 64 dims x 4
// support-groups of 8; fixed-order group combine ((g0+g1)+(g2+g3)).
// ---------------------------------------------------------------------------
__global__ __launch_bounds__(256) void centroid_sum_kernel(
    const float* __restrict__ z, const int* __restrict__ adec,
    float* __restrict__ protos)
{
    int c = blockIdx.x >> 4;
    int slice = blockIdx.x & 15;
    int dloc = threadIdx.x & 63;
    int g = threadIdx.x >> 6;          // support group 0..3
    int d = slice * 64 + dloc;
    const float* zs = z + (size_t)c * N_SUPPORT * Z_DIM;

    __shared__ unsigned int sm;
    if (threadIdx.x < 32) {
        int dec = adec[c * N_SUPPORT + threadIdx.x];
        unsigned int mm = __ballot_sync(0xffffffffu, dec != 0);
        if (threadIdx.x == 0) sm = mm;
    }
    __syncthreads();
    unsigned int m = sm;
    int cnt1 = __popc(m);
    int cnt0 = N_SUPPORT - cnt1;

    double s0 = 0.0, s1 = 0.0;
    #pragma unroll
    for (int j = 0; j < 8; j++) {
        int s = g * 8 + j;
        double v = (double)zs[(size_t)s * Z_DIM + d];
        if ((m >> s) & 1u) s1 += v; else s0 += v;
    }
    __shared__ double sh0[4][64], sh1[4][64];
    sh0[g][dloc] = s0;
    sh1[g][dloc] = s1;
    __syncthreads();

    if (threadIdx.x < 64) {
        int dd = threadIdx.x;
        double t0 = (sh0[0][dd] + sh0[1][dd]) + (sh0[2][dd] + sh0[3][dd]);
        double t1 = (sh1[0][dd] + sh1[1][dd]) + (sh1[2][dd] + sh1[3][dd]);
        int dg = slice * 64 + dd;
        float c0f = (cnt0 > 0) ? (float)(t0 / (double)(cnt0 > 1 ? cnt0 : 1))
                               : zs[dg];
        float c1f = (cnt1 > 0) ? (float)(t1 / (double)(cnt1 > 1 ? cnt1 : 1))
                               : zs[(size_t)Z_DIM + dg];
        protos[(size_t)(2 * c) * Z_DIM + dg]     = c0f;
        protos[(size_t)(2 * c + 1) * Z_DIM + dg] = c1f;
    }
}

// ---------------------------------------------------------------------------
// Fused: proto norms (fp64 tree) + proto bf16 triple split. One block/proto.
// ---------------------------------------------------------------------------
__global__ __launch_bounds__(256) void proto_split_sq_kernel(
    const float* __restrict__ protos,
    __nv_bfloat16* __restrict__ p0, __nv_bfloat16* __restrict__ p1,
    __nv_bfloat16* __restrict__ p2, float* __restrict__ proto_sq)
{
    int p = blockIdx.x;
    int tid = threadIdx.x;
    size_t o = (size_t)p * Z_DIM + tid * 4;
    float4 v = *(const float4*)(protos + o);
    ushort4 o0, o1, o2;
    split4v(v, o0, o1, o2);
    *(ushort4*)((unsigned short*)p0 + o) = o0;
    *(ushort4*)((unsigned short*)p1 + o) = o1;
    *(ushort4*)((unsigned short*)p2 + o) = o2;

    double s = 0.0;
    s = fma((double)v.x, (double)v.x, s);
    s = fma((double)v.y, (double)v.y, s);
    s = fma((double)v.z, (double)v.z, s);
    s = fma((double)v.w, (double)v.w, s);
    __shared__ double red[256];
    red[tid] = s;
    __syncthreads();
    for (int o2_ = 128; o2_ > 0; o2_ >>= 1) {
        if (tid < o2_) red[tid] += red[tid + o2_];
        __syncthreads();
    }
    if (tid == 0) proto_sq[p] = (float)red[0];
}

// ---------------------------------------------------------------------------
// Per-query loss + accuracy: one WARP per query, shuffle-only reductions.
// Epsilon-snapped argmax (first index on tie) identical to prior rounds.
// ---------------------------------------------------------------------------
__global__ __launch_bounds__(128) void loss_kernel(
    const float* __restrict__ dists,
    float* __restrict__ lpart, float* __restrict__ apart)
{
    const unsigned fm = 0xffffffffu;
    int w = threadIdx.x >> 5;
    int lane = threadIdx.x & 31;
    int q = blockIdx.x * 4 + w;

    float4 v = *(const float4*)(dists + (size_t)q * N_CLASS + lane * 4);

    // sum (deterministic fixed-order tree)
    float s = ((v.x + v.y) + (v.z + v.w));
    #pragma unroll
    for (int o = 16; o > 0; o >>= 1) s += __shfl_down_sync(fm, s, o);
    s = __shfl_sync(fm, s, 0);

    // max
    float m = fmaxf(fmaxf(v.x, v.y), fmaxf(v.z, v.w));
    #pragma unroll
    for (int o = 16; o > 0; o >>= 1) m = fmaxf(m, __shfl_down_sync(fm, m, o));
    m = __shfl_sync(fm, m, 0);

    // snapped argmax: smallest index within rel 3e-7 of max
    float thresh = fmaf(m, -3e-7f, m);
    int idx = N_CLASS + 1;
    if (v.w >= thresh) idx = lane * 4 + 3;
    if (v.z >= thresh) idx = lane * 4 + 2;
    if (v.y >= thresh) idx = lane * 4 + 1;
    if (v.x >= thresh) idx = lane * 4 + 0;
    #pragma unroll
    for (int o = 16; o > 0; o >>= 1) idx = min(idx, __shfl_down_sync(fm, idx, o));

    if (lane == 0) {
        int ct = q >> 7;
        float vt = dists[(size_t)q * N_CLASS + ct];
        lpart[q] = logf(s) - logf(vt);
        apart[q] = (idx == ct) ? 1.0f : 0.0f;
    }
}

// ---------------------------------------------------------------------------
// Deterministic final reduction (fp64).
// ---------------------------------------------------------------------------
__global__ __launch_bounds__(256) void final_kernel(
    const float* __restrict__ lpart, const float* __restrict__ apart,
    float* __restrict__ out)
{
    __shared__ double ls[256], as_[256];
    int tid = threadIdx.x;
    double l = 0.0, a = 0.0;
    int base = tid * (NQ_ROWS / 256);
    for (int i = 0; i < NQ_ROWS / 256; i++) {
        l += (double)lpart[base + i];
        a += (double)apart[base + i];
    }
    ls[tid] = l; as_[tid] = a;
    __syncthreads();
    for (int o = 128; o > 0; o >>= 1) {
        if (tid < o) { ls[tid] += ls[tid + o]; as_[tid] += as_[tid + o]; }
        __syncthreads();
    }
    if (tid == 0) {
        out[0] = (float)(ls[0] / (double)NQ_ROWS);
        out[1] = (float)(as_[0] / (double)NQ_ROWS);
    }
}

// ---------------------------------------------------------------------------
// Launch
// ---------------------------------------------------------------------------
extern "C" void kernel_launch(void* const* d_in, const int* in_sizes, int n_in,
                              void* d_out, int out_size)
{
    const float* xs = (const float*)d_in[0];
    const float* xq = (const float*)d_in[1];
    const float* W  = (const float*)d_in[2];
    float* out = (float*)d_out;

    float* z;        cudaGetSymbolAddress((void**)&z, g_z);
    float* protos;   cudaGetSymbolAddress((void**)&protos, g_protos);
    float* proto_sq; cudaGetSymbolAddress((void**)&proto_sq, g_proto_sq);
    float* qnorm;    cudaGetSymbolAddress((void**)&qnorm, g_qnorm);
    double* qpart;   cudaGetSymbolAddress((void**)&qpart, g_qpart);
    float* dists;    cudaGetSymbolAddress((void**)&dists, g_dists);
    float* lpart;    cudaGetSymbolAddress((void**)&lpart, g_lpart);
    float* apart;    cudaGetSymbolAddress((void**)&apart, g_apart);
    int* adec;       cudaGetSymbolAddress((void**)&adec, g_adec);
    __nv_bfloat16 *A0, *A1, *A2, *WT0, *WT1, *WT2;
    __nv_bfloat16 *Zq0, *Zq1, *Zq2, *P0, *P1, *P2;
    cudaGetSymbolAddress((void**)&A0, g_A0);
    cudaGetSymbolAddress((void**)&A1, g_A1);
    cudaGetSymbolAddress((void**)&A2, g_A2);
    cudaGetSymbolAddress((void**)&WT0, g_WT0);
    cudaGetSymbolAddress((void**)&WT1, g_WT1);
    cudaGetSymbolAddress((void**)&WT2, g_WT2);
    cudaGetSymbolAddress((void**)&Zq0, g_Zq0);
    cudaGetSymbolAddress((void**)&Zq1, g_Zq1);
    cudaGetSymbolAddress((void**)&Zq2, g_Zq2);
    cudaGetSymbolAddress((void**)&P0, g_P0);
    cudaGetSymbolAddress((void**)&P1, g_P1);
    cudaGetSymbolAddress((void**)&P2, g_P2);

    cudaFuncSetAttribute(gemm6_kernel<IN_DIM, 2>,
                         cudaFuncAttributeMaxDynamicSharedMemorySize, GT_SMEM);
    cudaFuncSetAttribute(gemm6_kernel<Z_DIM, 1>,
                         cudaFuncAttributeMaxDynamicSharedMemorySize, GT_SMEM);

    // 1) Split inputs into bf16 triples (merged xs+xq launch, 8 elems/thread)
    split_ab_kernel<<<(NZ_ROWS * IN_DIM) / 8 / 256, 256>>>(xs, xq, A0, A1, A2);
    split_wt_kernel<<<dim3(Z_DIM / 32, IN_DIM / 32), 256>>>(W, WT0, WT1, WT2);

    // 2) Projection GEMM with fused query-row split + partial norms
    gemm6_kernel<IN_DIM, 2><<<dim3(Z_DIM / 128, NZ_ROWS / 128), 256, GT_SMEM>>>(
        A0, A1, A2, WT0, WT1, WT2, z, nullptr, nullptr,
        Zq0, Zq1, Zq2, qpart);

    // 3) fused qnorm finalize + assignment (block-per-support-row);
    //    centroid sums (2048 blocks); proto split+norm
    post_gemm1_kernel<<<64 + NS_ROWS, 256>>>(qpart, qnorm, z, adec);
    centroid_sum_kernel<<<N_CLASS * 16, 256>>>(z, adec, protos);
    proto_split_sq_kernel<<<N_PROTO, 256>>>(protos, P0, P1, P2, proto_sq);

    // 4) Query-proto distances
    gemm6_kernel<Z_DIM, 1><<<dim3(N_PROTO / 128, NQ_ROWS / 128), 256, GT_SMEM>>>(
        Zq0, Zq1, Zq2, P0, P1, P2, dists, qnorm, proto_sq,
        nullptr, nullptr, nullptr, nullptr);

    // 5) Loss / acc (warp-per-query)
    loss_kernel<<<NQ_ROWS / 4, 128>>>(dists, lpart, apart);
    final_kernel<<<1, 256>>>(lpart, apart, out);
}

// round 15
// speedup vs baseline: 1.0447x; 1.0447x over previous
#include <cuda_runtime.h>
#include <cuda_bf16.h>
#include <math.h>
#include <stdint.h>

// ---------------------------------------------------------------------------
// Problem constants
// ---------------------------------------------------------------------------
#define N_CLASS   128
#define N_SUPPORT 32
#define N_QUERY   128
#define IN_DIM    2048
#define Z_DIM     1024
#define KCLUST    2

#define NS_ROWS (N_CLASS * N_SUPPORT)   // 4096
#define NQ_ROWS (N_CLASS * N_QUERY)    // 16384
#define NZ_ROWS (NS_ROWS + NQ_ROWS)    // 20480
#define N_PROTO (N_CLASS * KCLUST)     // 256

// ---------------------------------------------------------------------------
// Scratch (device globals; no allocation allowed)
// ---------------------------------------------------------------------------
__device__ float g_z[(size_t)NZ_ROWS * Z_DIM];          // fp32 z (support region used)
__device__ float g_protos[(size_t)N_PROTO * Z_DIM];
__device__ float g_proto_sq[N_PROTO];
__device__ float g_qnorm[NQ_ROWS];
__device__ double g_qpart[(size_t)NQ_ROWS * 8];         // per-coltile norm partials
__device__ float g_dists[(size_t)NQ_ROWS * N_CLASS];
__device__ float g_lpart[NQ_ROWS];
__device__ float g_apart[NQ_ROWS];
__device__ int g_adec[NS_ROWS];                         // per-support decision

// bf16 splits
__device__ __nv_bfloat16 g_A0[(size_t)NZ_ROWS * IN_DIM];
__device__ __nv_bfloat16 g_A1[(size_t)NZ_ROWS * IN_DIM];
__device__ __nv_bfloat16 g_A2[(size_t)NZ_ROWS * IN_DIM];
__device__ __nv_bfloat16 g_WT0[(size_t)Z_DIM * IN_DIM];
__device__ __nv_bfloat16 g_WT1[(size_t)Z_DIM * IN_DIM];
__device__ __nv_bfloat16 g_WT2[(size_t)Z_DIM * IN_DIM];
__device__ __nv_bfloat16 g_Zq0[(size_t)NQ_ROWS * Z_DIM];
__device__ __nv_bfloat16 g_Zq1[(size_t)NQ_ROWS * Z_DIM];
__device__ __nv_bfloat16 g_Zq2[(size_t)NQ_ROWS * Z_DIM];
__device__ __nv_bfloat16 g_P0[(size_t)N_PROTO * Z_DIM];
__device__ __nv_bfloat16 g_P1[(size_t)N_PROTO * Z_DIM];
__device__ __nv_bfloat16 g_P2[(size_t)N_PROTO * Z_DIM];

// ---------------------------------------------------------------------------
// Baseline-PTX helpers (mma.sync / ldmatrix / cp.async)
// ---------------------------------------------------------------------------
__device__ __forceinline__ uint32_t smem_u32(const void* p) {
    uint32_t a;
    asm("{ .reg .u64 t; cvta.to.shared.u64 t, %1; cvt.u32.u64 %0, t; }"
        : "=r"(a) : "l"(p));
    return a;
}

#define CP_ASYNC16(smem_addr, gptr) \
    asm volatile("cp.async.cg.shared.global [%0], [%1], 16;" \
                 :: "r"(smem_addr), "l"(gptr))
#define CP_COMMIT() asm volatile("cp.async.commit_group;" ::: "memory")
#define CP_WAIT1()  asm volatile("cp.async.wait_group 1;" ::: "memory")

#define LDSM_X4(r0, r1, r2, r3, addr) \
    asm volatile("ldmatrix.sync.aligned.m8n8.x4.shared.b16 {%0,%1,%2,%3}, [%4];" \
                 : "=r"(r0), "=r"(r1), "=r"(r2), "=r"(r3) : "r"(addr))

#define MMA_BF16(d0, d1, d2, d3, a0, a1, a2, a3, b0, b1) \
    asm volatile( \
        "mma.sync.aligned.m16n8k16.row.col.f32.bf16.bf16.f32 " \
        "{%0,%1,%2,%3}, {%4,%5,%6,%7}, {%8,%9}, {%0,%1,%2,%3};" \
        : "+f"(d0), "+f"(d1), "+f"(d2), "+f"(d3) \
        : "r"(a0), "r"(a1), "r"(a2), "r"(a3), "r"(b0), "r"(b1))

// Swizzled smem tile: logical [128 rows][64 B]; rows paired into 128B lines,
// 16B chunk cc = ((row&1)<<2)|c XOR-swizzled by (row>>1)&7.
__device__ __forceinline__ uint32_t tile_off(int row, int c) {
    int cc = ((row & 1) << 2) | c;
    int p  = cc ^ ((row >> 1) & 7);
    return (uint32_t)((row >> 1) * 128 + p * 16);
}

// ---------------------------------------------------------------------------
// bf16 3-way split helpers
// ---------------------------------------------------------------------------
__device__ __forceinline__ void split3(float x, unsigned short& s0,
                                       unsigned short& s1, unsigned short& s2)
{
    __nv_bfloat16 h0 = __float2bfloat16_rn(x);
    float r = x - __bfloat162float(h0);
    __nv_bfloat16 h1 = __float2bfloat16_rn(r);
    float r2 = r - __bfloat162float(h1);
    __nv_bfloat16 h2 = __float2bfloat16_rn(r2);
    s0 = __bfloat16_as_ushort(h0);
    s1 = __bfloat16_as_ushort(h1);
    s2 = __bfloat16_as_ushort(h2);
}

__device__ __forceinline__ void split4v(const float4& v, ushort4& o0,
                                        ushort4& o1, ushort4& o2)
{
    split3(v.x, o0.x, o1.x, o2.x);
    split3(v.y, o0.y, o1.y, o2.y);
    split3(v.z, o0.z, o1.z, o2.z);
    split3(v.w, o0.w, o1.w, o2.w);
}

// Merged split of A = [xs; xq]: 8 elems per thread, single launch.
__global__ __launch_bounds__(256) void split_ab_kernel(
    const float* __restrict__ xs, const float* __restrict__ xq,
    __nv_bfloat16* __restrict__ d0, __nv_bfloat16* __restrict__ d1,
    __nv_bfloat16* __restrict__ d2)
{
    const int NXS = NS_ROWS * IN_DIM;
    size_t i = ((size_t)blockIdx.x * 256 + threadIdx.x) * 8;
    const float* src = (i < (size_t)NXS) ? (xs + i) : (xq + (i - NXS));
    float4 va = *(const float4*)(src);
    float4 vb = *(const float4*)(src + 4);
    ushort4 a0, a1, a2, b0, b1, b2;
    split4v(va, a0, a1, a2);
    split4v(vb, b0, b1, b2);
    *(ushort4*)(d0 + i) = a0;
    *(ushort4*)(d0 + i + 4) = b0;
    *(ushort4*)(d1 + i) = a1;
    *(ushort4*)(d1 + i + 4) = b1;
    *(ushort4*)(d2 + i) = a2;
    *(ushort4*)(d2 + i + 4) = b2;
}

// Transpose + split W [2048 x 1024] -> WT splits [1024 x 2048].
__global__ __launch_bounds__(256) void split_wt_kernel(
    const float* __restrict__ W,
    __nv_bfloat16* __restrict__ t0, __nv_bfloat16* __restrict__ t1,
    __nv_bfloat16* __restrict__ t2)
{
    __shared__ float tile[32][33];
    int n0 = blockIdx.x * 32;
    int k0 = blockIdx.y * 32;
    int tx = threadIdx.x & 31;
    int ty0 = threadIdx.x >> 5;
    #pragma unroll
    for (int j = 0; j < 4; j++) {
        int ty = ty0 + j * 8;
        tile[ty][tx] = W[(size_t)(k0 + ty) * Z_DIM + n0 + tx];
    }
    __syncthreads();
    #pragma unroll
    for (int j = 0; j < 4; j++) {
        int ty = ty0 + j * 8;
        float x = tile[tx][ty];
        unsigned short s0, s1, s2;
        split3(x, s0, s1, s2);
        size_t o = (size_t)(n0 + ty) * IN_DIM + k0 + tx;
        t0[o] = __ushort_as_bfloat16(s0);
        t1[o] = __ushort_as_bfloat16(s1);
        t2[o] = __ushort_as_bfloat16(s2);
    }
}

// ---------------------------------------------------------------------------
// Unified bf16x6 split GEMM on HMMA, fp32 accumulate.
// CTA 128x128, BK=32, 2-stage cp.async pipeline (R9-proven structure:
// issue next -> commit -> wait_group 1 -> sync). 8 warps (2x4), warp 64x32.
// EPI=1: protonet dist epilogue.
// EPI=2: projection epilogue — support rows: plain fp32 store; query rows:
//        bf16 triple split + fp64 partial row norms (no fp32 store).
// ---------------------------------------------------------------------------
#define GT_TILE  8192                 // one split-tile: 128 rows x 64 B
#define GT_STAGE (6 * GT_TILE)        // 48 KB
#define GT_SMEM  (2 * GT_STAGE)       // 96 KB

template<int K_TOTAL, int EPI>
__global__ __launch_bounds__(256, 2) void gemm6_kernel(
    const __nv_bfloat16* __restrict__ A0, const __nv_bfloat16* __restrict__ A1,
    const __nv_bfloat16* __restrict__ A2,
    const __nv_bfloat16* __restrict__ B0, const __nv_bfloat16* __restrict__ B1,
    const __nv_bfloat16* __restrict__ B2,
    float* __restrict__ out,
    const float* __restrict__ qn, const float* __restrict__ pn,
    __nv_bfloat16* __restrict__ Q0, __nv_bfloat16* __restrict__ Q1,
    __nv_bfloat16* __restrict__ Q2, double* __restrict__ qpart)
{
    extern __shared__ char smem[];
    const uint32_t sb = smem_u32(smem);
    const int tid  = threadIdx.x;
    const int wid  = tid >> 5;
    const int lane = tid & 31;
    const int n0 = blockIdx.x * 128;
    const int m0 = blockIdx.y * 128;

    const int wm = wid & 1;
    const int wn = wid >> 1;
    const int mbase = wm * 64;
    const int nbase = wn * 32;

    const __nv_bfloat16* srcs[6];
    srcs[0] = A0 + (size_t)m0 * K_TOTAL;
    srcs[1] = A1 + (size_t)m0 * K_TOTAL;
    srcs[2] = A2 + (size_t)m0 * K_TOTAL;
    srcs[3] = B0 + (size_t)n0 * K_TOTAL;
    srcs[4] = B1 + (size_t)n0 * K_TOTAL;
    srcs[5] = B2 + (size_t)n0 * K_TOTAL;

    const int ldrow0 = tid >> 2;
    const int ldrow1 = (tid + 256) >> 2;
    const int ldc    = tid & 3;
    const uint32_t soff0 = tile_off(ldrow0, ldc);
    const uint32_t soff1 = tile_off(ldrow1, ldc);

    float acc[64];
    #pragma unroll
    for (int i = 0; i < 64; i++) acc[i] = 0.0f;

    // prologue: stage 0 <- chunk 0
    #pragma unroll
    for (int t = 0; t < 6; t++) {
        CP_ASYNC16(sb + t * GT_TILE + soff0,
                   srcs[t] + (size_t)ldrow0 * K_TOTAL + ldc * 8);
        CP_ASYNC16(sb + t * GT_TILE + soff1,
                   srcs[t] + (size_t)ldrow1 * K_TOTAL + ldc * 8);
    }
    CP_COMMIT();

    const int NCHUNK = K_TOTAL / 32;
    for (int chunk = 0; chunk < NCHUNK; chunk++) {
        // issue next chunk into the other stage (R9-proven ordering)
        if (chunk + 1 < NCHUNK) {
            uint32_t st = sb + ((chunk + 1) & 1) * GT_STAGE;
            size_t kn = (size_t)(chunk + 1) * 32;
            #pragma unroll
            for (int t = 0; t < 6; t++) {
                CP_ASYNC16(st + t * GT_TILE + soff0,
                           srcs[t] + (size_t)ldrow0 * K_TOTAL + kn + ldc * 8);
                CP_ASYNC16(st + t * GT_TILE + soff1,
                           srcs[t] + (size_t)ldrow1 * K_TOTAL + kn + ldc * 8);
            }
        }
        CP_COMMIT();
        CP_WAIT1();
        __syncthreads();

        uint32_t st = sb + (chunk & 1) * GT_STAGE;
        #pragma unroll
        for (int ks = 0; ks < 2; ks++) {
            uint32_t bfr[3][2][4];
            #pragma unroll
            for (int bj = 0; bj < 3; bj++) {
                #pragma unroll
                for (int q = 0; q < 2; q++) {
                    uint32_t off = tile_off(
                        nbase + (2 * q + (lane >> 4)) * 8 + (lane & 7),
                        ks * 2 + ((lane >> 3) & 1));
                    LDSM_X4(bfr[bj][q][0], bfr[bj][q][1],
                            bfr[bj][q][2], bfr[bj][q][3],
                            st + (3 + bj) * GT_TILE + off);
                }
            }
            #pragma unroll
            for (int ai = 0; ai < 3; ai++) {
                uint32_t af[4][4];
                #pragma unroll
                for (int mt = 0; mt < 4; mt++) {
                    uint32_t off = tile_off(mbase + mt * 16 + (lane & 15),
                                            ks * 2 + (lane >> 4));
                    LDSM_X4(af[mt][0], af[mt][1], af[mt][2], af[mt][3],
                            st + ai * GT_TILE + off);
                }
                #pragma unroll
                for (int bj = 0; bj < 3; bj++) {
                    if (ai + bj > 2) continue;
                    #pragma unroll
                    for (int mt = 0; mt < 4; mt++) {
                        #pragma unroll
                        for (int nt = 0; nt < 4; nt++) {
                            float* d = &acc[(mt * 4 + nt) * 4];
                            int q = nt >> 1, h = (nt & 1) * 2;
                            MMA_BF16(d[0], d[1], d[2], d[3],
                                     af[mt][0], af[mt][1], af[mt][2], af[mt][3],
                                     bfr[bj][q][h], bfr[bj][q][h + 1]);
                        }
                    }
                }
            }
        }
        __syncthreads();
    }

    if (EPI == 2) {
        if (m0 < NS_ROWS) {
            // support rows: plain fp32 store (feeds centroid path)
            #pragma unroll
            for (int mt = 0; mt < 4; mt++) {
                #pragma unroll
                for (int nt = 0; nt < 4; nt++) {
                    const float* d = &acc[(mt * 4 + nt) * 4];
                    int r0 = m0 + mbase + mt * 16 + (lane >> 2);
                    int cc = n0 + nbase + nt * 8 + (lane & 3) * 2;
                    *(float2*)(out + (size_t)r0 * Z_DIM + cc) =
                        make_float2(d[0], d[1]);
                    *(float2*)(out + (size_t)(r0 + 8) * Z_DIM + cc) =
                        make_float2(d[2], d[3]);
                }
            }
        } else {
            // query rows: bf16 triple split + fp64 partial norms, no fp32 z
            double* dpart = (double*)smem;   // [128 rows][4 wn]
            const unsigned fm = 0xffffffffu;
            #pragma unroll
            for (int mt = 0; mt < 4; mt++) {
                double rs0 = 0.0, rs1 = 0.0;
                int rl0 = mbase + mt * 16 + (lane >> 2);  // local row
                int q0r = m0 - NS_ROWS + rl0;
                #pragma unroll
                for (int nt = 0; nt < 4; nt++) {
                    const float* d = &acc[(mt * 4 + nt) * 4];
                    int cc = n0 + nbase + nt * 8 + (lane & 3) * 2;
                    unsigned short a0, b0, c0, a1, b1, c1;
                    split3(d[0], a0, b0, c0);
                    split3(d[1], a1, b1, c1);
                    *(ushort2*)((unsigned short*)Q0 + (size_t)q0r * Z_DIM + cc)
                        = make_ushort2(a0, a1);
                    *(ushort2*)((unsigned short*)Q1 + (size_t)q0r * Z_DIM + cc)
                        = make_ushort2(b0, b1);
                    *(ushort2*)((unsigned short*)Q2 + (size_t)q0r * Z_DIM + cc)
                        = make_ushort2(c0, c1);
                    rs0 += (double)d[0] * d[0] + (double)d[1] * d[1];
                    unsigned short a2, b2, c2, a3, b3, c3;
                    split3(d[2], a2, b2, c2);
                    split3(d[3], a3, b3, c3);
                    *(ushort2*)((unsigned short*)Q0 + (size_t)(q0r + 8) * Z_DIM + cc)
                        = make_ushort2(a2, a3);
                    *(ushort2*)((unsigned short*)Q1 + (size_t)(q0r + 8) * Z_DIM + cc)
                        = make_ushort2(b2, b3);
                    *(ushort2*)((unsigned short*)Q2 + (size_t)(q0r + 8) * Z_DIM + cc)
                        = make_ushort2(c2, c3);
                    rs1 += (double)d[2] * d[2] + (double)d[3] * d[3];
                }
                // reduce over the 4 lanes sharing each row
                rs0 += __shfl_down_sync(fm, rs0, 2);
                rs0 += __shfl_down_sync(fm, rs0, 1);
                rs1 += __shfl_down_sync(fm, rs1, 2);
                rs1 += __shfl_down_sync(fm, rs1, 1);
                if ((lane & 3) == 0) {
                    dpart[rl0 * 4 + wn]       = rs0;
                    dpart[(rl0 + 8) * 4 + wn] = rs1;
                }
            }
            __syncthreads();
            if (tid < 128) {
                double s = dpart[tid * 4 + 0] + dpart[tid * 4 + 1]
                         + dpart[tid * 4 + 2] + dpart[tid * 4 + 3];
                int q = m0 - NS_ROWS + tid;
                qpart[(size_t)q * 8 + blockIdx.x] = s;
            }
        }
    } else {
        // EPI == 1: protonet distance epilogue
        #pragma unroll
        for (int mt = 0; mt < 4; mt++) {
            int r0 = m0 + mbase + mt * 16 + (lane >> 2);
            float qv0 = qn[r0];
            float qv1 = qn[r0 + 8];
            #pragma unroll
            for (int nt = 0; nt < 4; nt++) {
                const float* d = &acc[(mt * 4 + nt) * 4];
                int cc = n0 + nbase + nt * 8 + (lane & 3) * 2;
                float p0 = pn[cc], p1 = pn[cc + 1];
                int cls = cc >> 1;
                float e0 = __fadd_rn(__fadd_rn(qv0, p0),
                                     -__fmul_rn(2.0f, d[0]));
                float e1 = __fadd_rn(__fadd_rn(qv0, p1),
                                     -__fmul_rn(2.0f, d[1]));
                out[(size_t)r0 * N_CLASS + cls] =
                    fminf(fmaxf(e0, 0.0f), fmaxf(e1, 0.0f));
                float e2 = __fadd_rn(__fadd_rn(qv1, p0),
                                     -__fmul_rn(2.0f, d[2]));
                float e3 = __fadd_rn(__fadd_rn(qv1, p1),
                                     -__fmul_rn(2.0f, d[3]));
                out[(size_t)(r0 + 8) * N_CLASS + cls] =
                    fminf(fmaxf(e2, 0.0f), fmaxf(e3, 0.0f));
            }
        }
    }
}

// ---------------------------------------------------------------------------
// Fused post-GEMM1 kernel: blocks [0,64) finalize query norms (fixed-order
// fp64 sum of 8 column-tile partials); blocks [64,576) compute per-support
// assignment decisions. fp32 fast path (4 independent partials, deterministic
// fixed-order combine) with guaranteed-safe margin test: fp32 error per
// distance is < 0.5 absolute, so |margin| >= 4.0 proves the fp64 decision.
// Rare near-ties recompute in exact fp64 (identical to prior rounds).
// ---------------------------------------------------------------------------
__global__ __launch_bounds__(256) void post_gemm1_kernel(
    const double* __restrict__ qpart, float* __restrict__ qn,
    const float* __restrict__ z, int* __restrict__ adec)
{
    if (blockIdx.x < 64) {
        int q = blockIdx.x * 256 + threadIdx.x;
        double s = 0.0;
        #pragma unroll
        for (int t = 0; t < 8; t++) s += qpart[(size_t)q * 8 + t];
        qn[q] = (float)s;
        return;
    }
    int b = blockIdx.x - 64;      // 0..511
    int c = b >> 2;               // class
    int wid = threadIdx.x >> 5;
    int lane = threadIdx.x & 31;
    int s = (b & 3) * 8 + wid;    // support 0..31
    const unsigned fmm = 0xffffffffu;

    const float* zs = z + (size_t)c * N_SUPPORT * Z_DIM;
    const float* zr = zs + (size_t)s * Z_DIM;

    // fp32 fast path: float4 loads, 4 independent partials per distance
    float f0a = 0.f, f0b = 0.f, f0c = 0.f, f0d = 0.f;
    float f1a = 0.f, f1b = 0.f, f1c = 0.f, f1d = 0.f;
    #pragma unroll
    for (int i = 0; i < 8; i++) {
        int d = (i * 32 + lane) * 4;
        float4 v  = *(const float4*)(zr + d);
        float4 i0 = *(const float4*)(zs + d);
        float4 i1 = *(const float4*)(zs + Z_DIM + d);
        float ax = v.x - i0.x, ay = v.y - i0.y;
        float az = v.z - i0.z, aw = v.w - i0.w;
        f0a = fmaf(ax, ax, f0a);
        f0b = fmaf(ay, ay, f0b);
        f0c = fmaf(az, az, f0c);
        f0d = fmaf(aw, aw, f0d);
        float bx = v.x - i1.x, by = v.y - i1.y;
        float bz = v.z - i1.z, bw = v.w - i1.w;
        f1a = fmaf(bx, bx, f1a);
        f1b = fmaf(by, by, f1b);
        f1c = fmaf(bz, bz, f1c);
        f1d = fmaf(bw, bw, f1d);
    }
    float f0 = (f0a + f0b) + (f0c + f0d);
    float f1 = (f1a + f1b) + (f1c + f1d);
    #pragma unroll
    for (int o = 16; o > 0; o >>= 1) {
        f0 += __shfl_down_sync(fmm, f0, o);
        f1 += __shfl_down_sync(fmm, f1, o);
    }
    f0 = __shfl_sync(fmm, f0, 0);
    f1 = __shfl_sync(fmm, f1, 0);

    float margin = f1 - f0;
    if (fabsf(margin) >= 4.0f) {
        // fp32 error bound (<0.5 per distance) proves the exact decision
        if (lane == 0) adec[c * N_SUPPORT + s] = (margin < 0.0f) ? 1 : 0;
        return;
    }

    // rare near-tie: exact fp64 recompute (deterministic fixed order)
    double d0 = 0.0, d1 = 0.0;
    for (int d = lane; d < Z_DIM; d += 32) {
        double v = (double)zr[d];
        double a = v - (double)zs[d];
        double bb = v - (double)zs[(size_t)Z_DIM + d];
        d0 = fma(a, a, d0);
        d1 = fma(bb, bb, d1);
    }
    #pragma unroll
    for (int o = 16; o > 0; o >>= 1) {
        d0 += __shfl_down_sync(fmm, d0, o);
        d1 += __shfl_down_sync(fmm, d1, o);
    }
    if (lane == 0) adec[c * N_SUPPORT + s] = (d1 < d0) ? 1 : 0;
}

// ---------------------------------------------------------------------------
// Centroid sums per dim-slice (mask rebuilt in-block via warp-0 ballot).
// grid 512 = class*4 + slice. (R12-proven version, fp64 exact.)
// ---------------------------------------------------------------------------
__global__ __launch_bounds__(256) void centroid_sum_kernel(
    const float* __restrict__ z, const int* __restrict__ adec,
    float* __restrict__ protos)
{
    int c = blockIdx.x >> 2;
    int slice = blockIdx.x & 3;
    int d = slice * 256 + threadIdx.x;
    const float* zs = z + (size_t)c * N_SUPPORT * Z_DIM;

    __shared__ unsigned int sm;
    if (threadIdx.x < 32) {
        int dec = adec[c * N_SUPPORT + threadIdx.x];
        unsigned int mm = __ballot_sync(0xffffffffu, dec != 0);
        if (threadIdx.x == 0) sm = mm;
    }
    __syncthreads();
    unsigned int m = sm;
    int cnt1 = __popc(m);
    int cnt0 = N_SUPPORT - cnt1;

    double s0 = 0.0, s1 = 0.0;
    #pragma unroll 4
    for (int s = 0; s < N_SUPPORT; s++) {
        double v = (double)zs[(size_t)s * Z_DIM + d];
        if ((m >> s) & 1u) s1 += v; else s0 += v;
    }
    float c0f = (cnt0 > 0) ? (float)(s0 / (double)(cnt0 > 1 ? cnt0 : 1)) : zs[d];
    float c1f = (cnt1 > 0) ? (float)(s1 / (double)(cnt1 > 1 ? cnt1 : 1))
                           : zs[(size_t)Z_DIM + d];
    protos[(size_t)(2 * c) * Z_DIM + d]     = c0f;
    protos[(size_t)(2 * c + 1) * Z_DIM + d] = c1f;
}

// ---------------------------------------------------------------------------
// Fused: proto norms (fp64 tree) + proto bf16 triple split. One block/proto.
// ---------------------------------------------------------------------------
__global__ __launch_bounds__(256) void proto_split_sq_kernel(
    const float* __restrict__ protos,
    __nv_bfloat16* __restrict__ p0, __nv_bfloat16* __restrict__ p1,
    __nv_bfloat16* __restrict__ p2, float* __restrict__ proto_sq)
{
    int p = blockIdx.x;
    int tid = threadIdx.x;
    size_t o = (size_t)p * Z_DIM + tid * 4;
    float4 v = *(const float4*)(protos + o);
    ushort4 o0, o1, o2;
    split4v(v, o0, o1, o2);
    *(ushort4*)((unsigned short*)p0 + o) = o0;
    *(ushort4*)((unsigned short*)p1 + o) = o1;
    *(ushort4*)((unsigned short*)p2 + o) = o2;

    double s = 0.0;
    s = fma((double)v.x, (double)v.x, s);
    s = fma((double)v.y, (double)v.y, s);
    s = fma((double)v.z, (double)v.z, s);
    s = fma((double)v.w, (double)v.w, s);
    __shared__ double red[256];
    red[tid] = s;
    __syncthreads();
    for (int o2_ = 128; o2_ > 0; o2_ >>= 1) {
        if (tid < o2_) red[tid] += red[tid + o2_];
        __syncthreads();
    }
    if (tid == 0) proto_sq[p] = (float)red[0];
}

// ---------------------------------------------------------------------------
// Per-query loss + accuracy: one WARP per query, shuffle-only reductions.
// Epsilon-snapped argmax (first index on tie) identical to prior rounds.
// ---------------------------------------------------------------------------
__global__ __launch_bounds__(128) void loss_kernel(
    const float* __restrict__ dists,
    float* __restrict__ lpart, float* __restrict__ apart)
{
    const unsigned fm = 0xffffffffu;
    int w = threadIdx.x >> 5;
    int lane = threadIdx.x & 31;
    int q = blockIdx.x * 4 + w;

    float4 v = *(const float4*)(dists + (size_t)q * N_CLASS + lane * 4);

    // sum (deterministic fixed-order tree)
    float s = ((v.x + v.y) + (v.z + v.w));
    #pragma unroll
    for (int o = 16; o > 0; o >>= 1) s += __shfl_down_sync(fm, s, o);
    s = __shfl_sync(fm, s, 0);

    // max
    float m = fmaxf(fmaxf(v.x, v.y), fmaxf(v.z, v.w));
    #pragma unroll
    for (int o = 16; o > 0; o >>= 1) m = fmaxf(m, __shfl_down_sync(fm, m, o));
    m = __shfl_sync(fm, m, 0);

    // snapped argmax: smallest index within rel 3e-7 of max
    float thresh = fmaf(m, -3e-7f, m);
    int idx = N_CLASS + 1;
    if (v.w >= thresh) idx = lane * 4 + 3;
    if (v.z >= thresh) idx = lane * 4 + 2;
    if (v.y >= thresh) idx = lane * 4 + 1;
    if (v.x >= thresh) idx = lane * 4 + 0;
    #pragma unroll
    for (int o = 16; o > 0; o >>= 1) idx = min(idx, __shfl_down_sync(fm, idx, o));

    if (lane == 0) {
        int ct = q >> 7;
        float vt = dists[(size_t)q * N_CLASS + ct];
        lpart[q] = logf(s) - logf(vt);
        apart[q] = (idx == ct) ? 1.0f : 0.0f;
    }
}

// ---------------------------------------------------------------------------
// Deterministic final reduction (fp64).
// ---------------------------------------------------------------------------
__global__ __launch_bounds__(256) void final_kernel(
    const float* __restrict__ lpart, const float* __restrict__ apart,
    float* __restrict__ out)
{
    __shared__ double ls[256], as_[256];
    int tid = threadIdx.x;
    double l = 0.0, a = 0.0;
    int base = tid * (NQ_ROWS / 256);
    for (int i = 0; i < NQ_ROWS / 256; i++) {
        l += (double)lpart[base + i];
        a += (double)apart[base + i];
    }
    ls[tid] = l; as_[tid] = a;
    __syncthreads();
    for (int o = 128; o > 0; o >>= 1) {
        if (tid < o) { ls[tid] += ls[tid + o]; as_[tid] += as_[tid + o]; }
        __syncthreads();
    }
    if (tid == 0) {
        out[0] = (float)(ls[0] / (double)NQ_ROWS);
        out[1] = (float)(as_[0] / (double)NQ_ROWS);
    }
}

// ---------------------------------------------------------------------------
// Launch
// ---------------------------------------------------------------------------
extern "C" void kernel_launch(void* const* d_in, const int* in_sizes, int n_in,
                              void* d_out, int out_size)
{
    const float* xs = (const float*)d_in[0];
    const float* xq = (const float*)d_in[1];
    const float* W  = (const float*)d_in[2];
    float* out = (float*)d_out;

    float* z;        cudaGetSymbolAddress((void**)&z, g_z);
    float* protos;   cudaGetSymbolAddress((void**)&protos, g_protos);
    float* proto_sq; cudaGetSymbolAddress((void**)&proto_sq, g_proto_sq);
    float* qnorm;    cudaGetSymbolAddress((void**)&qnorm, g_qnorm);
    double* qpart;   cudaGetSymbolAddress((void**)&qpart, g_qpart);
    float* dists;    cudaGetSymbolAddress((void**)&dists, g_dists);
    float* lpart;    cudaGetSymbolAddress((void**)&lpart, g_lpart);
    float* apart;    cudaGetSymbolAddress((void**)&apart, g_apart);
    int* adec;       cudaGetSymbolAddress((void**)&adec, g_adec);
    __nv_bfloat16 *A0, *A1, *A2, *WT0, *WT1, *WT2;
    __nv_bfloat16 *Zq0, *Zq1, *Zq2, *P0, *P1, *P2;
    cudaGetSymbolAddress((void**)&A0, g_A0);
    cudaGetSymbolAddress((void**)&A1, g_A1);
    cudaGetSymbolAddress((void**)&A2, g_A2);
    cudaGetSymbolAddress((void**)&WT0, g_WT0);
    cudaGetSymbolAddress((void**)&WT1, g_WT1);
    cudaGetSymbolAddress((void**)&WT2, g_WT2);
    cudaGetSymbolAddress((void**)&Zq0, g_Zq0);
    cudaGetSymbolAddress((void**)&Zq1, g_Zq1);
    cudaGetSymbolAddress((void**)&Zq2, g_Zq2);
    cudaGetSymbolAddress((void**)&P0, g_P0);
    cudaGetSymbolAddress((void**)&P1, g_P1);
    cudaGetSymbolAddress((void**)&P2, g_P2);

    cudaFuncSetAttribute(gemm6_kernel<IN_DIM, 2>,
                         cudaFuncAttributeMaxDynamicSharedMemorySize, GT_SMEM);
    cudaFuncSetAttribute(gemm6_kernel<Z_DIM, 1>,
                         cudaFuncAttributeMaxDynamicSharedMemorySize, GT_SMEM);

    // 1) Split inputs into bf16 triples (merged xs+xq launch, 8 elems/thread)
    split_ab_kernel<<<(NZ_ROWS * IN_DIM) / 8 / 256, 256>>>(xs, xq, A0, A1, A2);
    split_wt_kernel<<<dim3(Z_DIM / 32, IN_DIM / 32), 256>>>(W, WT0, WT1, WT2);

    // 2) Projection GEMM with fused query-row split + partial norms
    gemm6_kernel<IN_DIM, 2><<<dim3(Z_DIM / 128, NZ_ROWS / 128), 256, GT_SMEM>>>(
        A0, A1, A2, WT0, WT1, WT2, z, nullptr, nullptr,
        Zq0, Zq1, Zq2, qpart);

    // 3) fused qnorm finalize + assignment (fp32 fast path + fp64 fallback);
    //    centroid sums; proto split+norm
    post_gemm1_kernel<<<64 + N_CLASS * 4, 256>>>(qpart, qnorm, z, adec);
    centroid_sum_kernel<<<N_CLASS * 4, 256>>>(z, adec, protos);
    proto_split_sq_kernel<<<N_PROTO, 256>>>(protos, P0, P1, P2, proto_sq);

    // 4) Query-proto distances
    gemm6_kernel<Z_DIM, 1><<<dim3(N_PROTO / 128, NQ_ROWS / 128), 256, GT_SMEM>>>(
        Zq0, Zq1, Zq2, P0, P1, P2, dists, qnorm, proto_sq,
        nullptr, nullptr, nullptr, nullptr);

    // 5) Loss / acc (warp-per-query)
    loss_kernel<<<NQ_ROWS / 4, 128>>>(dists, lpart, apart);
    final_kernel<<<1, 256>>>(lpart, apart, out);
}

// round 16
// speedup vs baseline: 1.0675x; 1.0218x over previous
#include <cuda_runtime.h>
#include <cuda_bf16.h>
#include <math.h>
#include <stdint.h>

// ---------------------------------------------------------------------------
// Problem constants
// ---------------------------------------------------------------------------
#define N_CLASS   128
#define N_SUPPORT 32
#define N_QUERY   128
#define IN_DIM    2048
#define Z_DIM     1024
#define KCLUST    2

#define NS_ROWS (N_CLASS * N_SUPPORT)   // 4096
#define NQ_ROWS (N_CLASS * N_QUERY)    // 16384
#define NZ_ROWS (NS_ROWS + NQ_ROWS)    // 20480
#define N_PROTO (N_CLASS * KCLUST)     // 256

// ---------------------------------------------------------------------------
// Scratch (device globals; no allocation allowed)
// ---------------------------------------------------------------------------
__device__ float g_proto_sq[N_PROTO];
__device__ double g_ppart[N_PROTO * 4];                 // per-slice norm partials
__device__ float g_qnorm[NQ_ROWS];
__device__ double g_qpart[(size_t)NQ_ROWS * 8];         // per-coltile norm partials
__device__ float g_z[(size_t)NZ_ROWS * Z_DIM];          // fp32 z (support region used)
__device__ float g_dists[(size_t)NQ_ROWS * N_CLASS];
__device__ float g_lpart[NQ_ROWS];
__device__ float g_apart[NQ_ROWS];
__device__ int g_adec[NS_ROWS];                         // per-support decision

// bf16 splits
__device__ __nv_bfloat16 g_A0[(size_t)NZ_ROWS * IN_DIM];
__device__ __nv_bfloat16 g_A1[(size_t)NZ_ROWS * IN_DIM];
__device__ __nv_bfloat16 g_A2[(size_t)NZ_ROWS * IN_DIM];
__device__ __nv_bfloat16 g_WT0[(size_t)Z_DIM * IN_DIM];
__device__ __nv_bfloat16 g_WT1[(size_t)Z_DIM * IN_DIM];
__device__ __nv_bfloat16 g_WT2[(size_t)Z_DIM * IN_DIM];
__device__ __nv_bfloat16 g_Zq0[(size_t)NQ_ROWS * Z_DIM];
__device__ __nv_bfloat16 g_Zq1[(size_t)NQ_ROWS * Z_DIM];
__device__ __nv_bfloat16 g_Zq2[(size_t)NQ_ROWS * Z_DIM];
__device__ __nv_bfloat16 g_P0[(size_t)N_PROTO * Z_DIM];
__device__ __nv_bfloat16 g_P1[(size_t)N_PROTO * Z_DIM];
__device__ __nv_bfloat16 g_P2[(size_t)N_PROTO * Z_DIM];

// ---------------------------------------------------------------------------
// Baseline-PTX helpers (mma.sync / ldmatrix / cp.async)
// ---------------------------------------------------------------------------
__device__ __forceinline__ uint32_t smem_u32(const void* p) {
    uint32_t a;
    asm("{ .reg .u64 t; cvta.to.shared.u64 t, %1; cvt.u32.u64 %0, t; }"
        : "=r"(a) : "l"(p));
    return a;
}

#define CP_ASYNC16(smem_addr, gptr) \
    asm volatile("cp.async.cg.shared.global [%0], [%1], 16;" \
                 :: "r"(smem_addr), "l"(gptr))
#define CP_COMMIT() asm volatile("cp.async.commit_group;" ::: "memory")
#define CP_WAIT1()  asm volatile("cp.async.wait_group 1;" ::: "memory")

#define LDSM_X4(r0, r1, r2, r3, addr) \
    asm volatile("ldmatrix.sync.aligned.m8n8.x4.shared.b16 {%0,%1,%2,%3}, [%4];" \
                 : "=r"(r0), "=r"(r1), "=r"(r2), "=r"(r3) : "r"(addr))

#define MMA_BF16(d0, d1, d2, d3, a0, a1, a2, a3, b0, b1) \
    asm volatile( \
        "mma.sync.aligned.m16n8k16.row.col.f32.bf16.bf16.f32 " \
        "{%0,%1,%2,%3}, {%4,%5,%6,%7}, {%8,%9}, {%0,%1,%2,%3};" \
        : "+f"(d0), "+f"(d1), "+f"(d2), "+f"(d3) \
        : "r"(a0), "r"(a1), "r"(a2), "r"(a3), "r"(b0), "r"(b1))

// Swizzled smem tile: logical [128 rows][64 B]; rows paired into 128B lines,
// 16B chunk cc = ((row&1)<<2)|c XOR-swizzled by (row>>1)&7.
__device__ __forceinline__ uint32_t tile_off(int row, int c) {
    int cc = ((row & 1) << 2) | c;
    int p  = cc ^ ((row >> 1) & 7);
    return (uint32_t)((row >> 1) * 128 + p * 16);
}

// ---------------------------------------------------------------------------
// bf16 3-way split helpers
// ---------------------------------------------------------------------------
__device__ __forceinline__ void split3(float x, unsigned short& s0,
                                       unsigned short& s1, unsigned short& s2)
{
    __nv_bfloat16 h0 = __float2bfloat16_rn(x);
    float r = x - __bfloat162float(h0);
    __nv_bfloat16 h1 = __float2bfloat16_rn(r);
    float r2 = r - __bfloat162float(h1);
    __nv_bfloat16 h2 = __float2bfloat16_rn(r2);
    s0 = __bfloat16_as_ushort(h0);
    s1 = __bfloat16_as_ushort(h1);
    s2 = __bfloat16_as_ushort(h2);
}

__device__ __forceinline__ void split4v(const float4& v, ushort4& o0,
                                        ushort4& o1, ushort4& o2)
{
    split3(v.x, o0.x, o1.x, o2.x);
    split3(v.y, o0.y, o1.y, o2.y);
    split3(v.z, o0.z, o1.z, o2.z);
    split3(v.w, o0.w, o1.w, o2.w);
}

// Merged split of A = [xs; xq]: 8 elems per thread, single launch.
__global__ __launch_bounds__(256) void split_ab_kernel(
    const float* __restrict__ xs, const float* __restrict__ xq,
    __nv_bfloat16* __restrict__ d0, __nv_bfloat16* __restrict__ d1,
    __nv_bfloat16* __restrict__ d2)
{
    const int NXS = NS_ROWS * IN_DIM;
    size_t i = ((size_t)blockIdx.x * 256 + threadIdx.x) * 8;
    const float* src = (i < (size_t)NXS) ? (xs + i) : (xq + (i - NXS));
    float4 va = *(const float4*)(src);
    float4 vb = *(const float4*)(src + 4);
    ushort4 a0, a1, a2, b0, b1, b2;
    split4v(va, a0, a1, a2);
    split4v(vb, b0, b1, b2);
    *(ushort4*)(d0 + i) = a0;
    *(ushort4*)(d0 + i + 4) = b0;
    *(ushort4*)(d1 + i) = a1;
    *(ushort4*)(d1 + i + 4) = b1;
    *(ushort4*)(d2 + i) = a2;
    *(ushort4*)(d2 + i + 4) = b2;
}

// Transpose + split W [2048 x 1024] -> WT splits [1024 x 2048].
__global__ __launch_bounds__(256) void split_wt_kernel(
    const float* __restrict__ W,
    __nv_bfloat16* __restrict__ t0, __nv_bfloat16* __restrict__ t1,
    __nv_bfloat16* __restrict__ t2)
{
    __shared__ float tile[32][33];
    int n0 = blockIdx.x * 32;
    int k0 = blockIdx.y * 32;
    int tx = threadIdx.x & 31;
    int ty0 = threadIdx.x >> 5;
    #pragma unroll
    for (int j = 0; j < 4; j++) {
        int ty = ty0 + j * 8;
        tile[ty][tx] = W[(size_t)(k0 + ty) * Z_DIM + n0 + tx];
    }
    __syncthreads();
    #pragma unroll
    for (int j = 0; j < 4; j++) {
        int ty = ty0 + j * 8;
        float x = tile[tx][ty];
        unsigned short s0, s1, s2;
        split3(x, s0, s1, s2);
        size_t o = (size_t)(n0 + ty) * IN_DIM + k0 + tx;
        t0[o] = __ushort_as_bfloat16(s0);
        t1[o] = __ushort_as_bfloat16(s1);
        t2[o] = __ushort_as_bfloat16(s2);
    }
}

// ---------------------------------------------------------------------------
// Unified bf16x6 split GEMM on HMMA, fp32 accumulate.
// CTA 128x128, BK=32, 2-stage cp.async pipeline (R9-proven structure:
// issue next -> commit -> wait_group 1 -> sync). 8 warps (2x4), warp 64x32.
// EPI=1: protonet dist epilogue.
// EPI=2: projection epilogue — support rows: plain fp32 store; query rows:
//        bf16 triple split + fp64 partial row norms (no fp32 store).
// ---------------------------------------------------------------------------
#define GT_TILE  8192                 // one split-tile: 128 rows x 64 B
#define GT_STAGE (6 * GT_TILE)        // 48 KB
#define GT_SMEM  (2 * GT_STAGE)       // 96 KB

template<int K_TOTAL, int EPI>
__global__ __launch_bounds__(256, 2) void gemm6_kernel(
    const __nv_bfloat16* __restrict__ A0, const __nv_bfloat16* __restrict__ A1,
    const __nv_bfloat16* __restrict__ A2,
    const __nv_bfloat16* __restrict__ B0, const __nv_bfloat16* __restrict__ B1,
    const __nv_bfloat16* __restrict__ B2,
    float* __restrict__ out,
    const float* __restrict__ qn, const float* __restrict__ pn,
    __nv_bfloat16* __restrict__ Q0, __nv_bfloat16* __restrict__ Q1,
    __nv_bfloat16* __restrict__ Q2, double* __restrict__ qpart)
{
    extern __shared__ char smem[];
    const uint32_t sb = smem_u32(smem);
    const int tid  = threadIdx.x;
    const int wid  = tid >> 5;
    const int lane = tid & 31;
    const int n0 = blockIdx.x * 128;
    const int m0 = blockIdx.y * 128;

    const int wm = wid & 1;
    const int wn = wid >> 1;
    const int mbase = wm * 64;
    const int nbase = wn * 32;

    const __nv_bfloat16* srcs[6];
    srcs[0] = A0 + (size_t)m0 * K_TOTAL;
    srcs[1] = A1 + (size_t)m0 * K_TOTAL;
    srcs[2] = A2 + (size_t)m0 * K_TOTAL;
    srcs[3] = B0 + (size_t)n0 * K_TOTAL;
    srcs[4] = B1 + (size_t)n0 * K_TOTAL;
    srcs[5] = B2 + (size_t)n0 * K_TOTAL;

    const int ldrow0 = tid >> 2;
    const int ldrow1 = (tid + 256) >> 2;
    const int ldc    = tid & 3;
    const uint32_t soff0 = tile_off(ldrow0, ldc);
    const uint32_t soff1 = tile_off(ldrow1, ldc);

    float acc[64];
    #pragma unroll
    for (int i = 0; i < 64; i++) acc[i] = 0.0f;

    // prologue: stage 0 <- chunk 0
    #pragma unroll
    for (int t = 0; t < 6; t++) {
        CP_ASYNC16(sb + t * GT_TILE + soff0,
                   srcs[t] + (size_t)ldrow0 * K_TOTAL + ldc * 8);
        CP_ASYNC16(sb + t * GT_TILE + soff1,
                   srcs[t] + (size_t)ldrow1 * K_TOTAL + ldc * 8);
    }
    CP_COMMIT();

    const int NCHUNK = K_TOTAL / 32;
    for (int chunk = 0; chunk < NCHUNK; chunk++) {
        // issue next chunk into the other stage (R9-proven ordering)
        if (chunk + 1 < NCHUNK) {
            uint32_t st = sb + ((chunk + 1) & 1) * GT_STAGE;
            size_t kn = (size_t)(chunk + 1) * 32;
            #pragma unroll
            for (int t = 0; t < 6; t++) {
                CP_ASYNC16(st + t * GT_TILE + soff0,
                           srcs[t] + (size_t)ldrow0 * K_TOTAL + kn + ldc * 8);
                CP_ASYNC16(st + t * GT_TILE + soff1,
                           srcs[t] + (size_t)ldrow1 * K_TOTAL + kn + ldc * 8);
            }
        }
        CP_COMMIT();
        CP_WAIT1();
        __syncthreads();

        uint32_t st = sb + (chunk & 1) * GT_STAGE;
        #pragma unroll
        for (int ks = 0; ks < 2; ks++) {
            uint32_t bfr[3][2][4];
            #pragma unroll
            for (int bj = 0; bj < 3; bj++) {
                #pragma unroll
                for (int q = 0; q < 2; q++) {
                    uint32_t off = tile_off(
                        nbase + (2 * q + (lane >> 4)) * 8 + (lane & 7),
                        ks * 2 + ((lane >> 3) & 1));
                    LDSM_X4(bfr[bj][q][0], bfr[bj][q][1],
                            bfr[bj][q][2], bfr[bj][q][3],
                            st + (3 + bj) * GT_TILE + off);
                }
            }
            #pragma unroll
            for (int ai = 0; ai < 3; ai++) {
                uint32_t af[4][4];
                #pragma unroll
                for (int mt = 0; mt < 4; mt++) {
                    uint32_t off = tile_off(mbase + mt * 16 + (lane & 15),
                                            ks * 2 + (lane >> 4));
                    LDSM_X4(af[mt][0], af[mt][1], af[mt][2], af[mt][3],
                            st + ai * GT_TILE + off);
                }
                #pragma unroll
                for (int bj = 0; bj < 3; bj++) {
                    if (ai + bj > 2) continue;
                    #pragma unroll
                    for (int mt = 0; mt < 4; mt++) {
                        #pragma unroll
                        for (int nt = 0; nt < 4; nt++) {
                            float* d = &acc[(mt * 4 + nt) * 4];
                            int q = nt >> 1, h = (nt & 1) * 2;
                            MMA_BF16(d[0], d[1], d[2], d[3],
                                     af[mt][0], af[mt][1], af[mt][2], af[mt][3],
                                     bfr[bj][q][h], bfr[bj][q][h + 1]);
                        }
                    }
                }
            }
        }
        __syncthreads();
    }

    if (EPI == 2) {
        if (m0 < NS_ROWS) {
            // support rows: plain fp32 store (feeds centroid path)
            #pragma unroll
            for (int mt = 0; mt < 4; mt++) {
                #pragma unroll
                for (int nt = 0; nt < 4; nt++) {
                    const float* d = &acc[(mt * 4 + nt) * 4];
                    int r0 = m0 + mbase + mt * 16 + (lane >> 2);
                    int cc = n0 + nbase + nt * 8 + (lane & 3) * 2;
                    *(float2*)(out + (size_t)r0 * Z_DIM + cc) =
                        make_float2(d[0], d[1]);
                    *(float2*)(out + (size_t)(r0 + 8) * Z_DIM + cc) =
                        make_float2(d[2], d[3]);
                }
            }
        } else {
            // query rows: bf16 triple split + fp64 partial norms, no fp32 z
            double* dpart = (double*)smem;   // [128 rows][4 wn]
            const unsigned fm = 0xffffffffu;
            #pragma unroll
            for (int mt = 0; mt < 4; mt++) {
                double rs0 = 0.0, rs1 = 0.0;
                int rl0 = mbase + mt * 16 + (lane >> 2);  // local row
                int q0r = m0 - NS_ROWS + rl0;
                #pragma unroll
                for (int nt = 0; nt < 4; nt++) {
                    const float* d = &acc[(mt * 4 + nt) * 4];
                    int cc = n0 + nbase + nt * 8 + (lane & 3) * 2;
                    unsigned short a0, b0, c0, a1, b1, c1;
                    split3(d[0], a0, b0, c0);
                    split3(d[1], a1, b1, c1);
                    *(ushort2*)((unsigned short*)Q0 + (size_t)q0r * Z_DIM + cc)
                        = make_ushort2(a0, a1);
                    *(ushort2*)((unsigned short*)Q1 + (size_t)q0r * Z_DIM + cc)
                        = make_ushort2(b0, b1);
                    *(ushort2*)((unsigned short*)Q2 + (size_t)q0r * Z_DIM + cc)
                        = make_ushort2(c0, c1);
                    rs0 += (double)d[0] * d[0] + (double)d[1] * d[1];
                    unsigned short a2, b2, c2, a3, b3, c3;
                    split3(d[2], a2, b2, c2);
                    split3(d[3], a3, b3, c3);
                    *(ushort2*)((unsigned short*)Q0 + (size_t)(q0r + 8) * Z_DIM + cc)
                        = make_ushort2(a2, a3);
                    *(ushort2*)((unsigned short*)Q1 + (size_t)(q0r + 8) * Z_DIM + cc)
                        = make_ushort2(b2, b3);
                    *(ushort2*)((unsigned short*)Q2 + (size_t)(q0r + 8) * Z_DIM + cc)
                        = make_ushort2(c2, c3);
                    rs1 += (double)d[2] * d[2] + (double)d[3] * d[3];
                }
                // reduce over the 4 lanes sharing each row
                rs0 += __shfl_down_sync(fm, rs0, 2);
                rs0 += __shfl_down_sync(fm, rs0, 1);
                rs1 += __shfl_down_sync(fm, rs1, 2);
                rs1 += __shfl_down_sync(fm, rs1, 1);
                if ((lane & 3) == 0) {
                    dpart[rl0 * 4 + wn]       = rs0;
                    dpart[(rl0 + 8) * 4 + wn] = rs1;
                }
            }
            __syncthreads();
            if (tid < 128) {
                double s = dpart[tid * 4 + 0] + dpart[tid * 4 + 1]
                         + dpart[tid * 4 + 2] + dpart[tid * 4 + 3];
                int q = m0 - NS_ROWS + tid;
                qpart[(size_t)q * 8 + blockIdx.x] = s;
            }
        }
    } else {
        // EPI == 1: protonet distance epilogue
        #pragma unroll
        for (int mt = 0; mt < 4; mt++) {
            int r0 = m0 + mbase + mt * 16 + (lane >> 2);
            float qv0 = qn[r0];
            float qv1 = qn[r0 + 8];
            #pragma unroll
            for (int nt = 0; nt < 4; nt++) {
                const float* d = &acc[(mt * 4 + nt) * 4];
                int cc = n0 + nbase + nt * 8 + (lane & 3) * 2;
                float p0 = pn[cc], p1 = pn[cc + 1];
                int cls = cc >> 1;
                float e0 = __fadd_rn(__fadd_rn(qv0, p0),
                                     -__fmul_rn(2.0f, d[0]));
                float e1 = __fadd_rn(__fadd_rn(qv0, p1),
                                     -__fmul_rn(2.0f, d[1]));
                out[(size_t)r0 * N_CLASS + cls] =
                    fminf(fmaxf(e0, 0.0f), fmaxf(e1, 0.0f));
                float e2 = __fadd_rn(__fadd_rn(qv1, p0),
                                     -__fmul_rn(2.0f, d[2]));
                float e3 = __fadd_rn(__fadd_rn(qv1, p1),
                                     -__fmul_rn(2.0f, d[3]));
                out[(size_t)(r0 + 8) * N_CLASS + cls] =
                    fminf(fmaxf(e2, 0.0f), fmaxf(e3, 0.0f));
            }
        }
    }
}

// ---------------------------------------------------------------------------
// Fused post-GEMM1 kernel: blocks [0,64) finalize query norms (fixed-order
// fp64 sum of 8 column-tile partials); blocks [64,576) compute per-support
// assignment decisions. fp32 fast path (4 independent partials, deterministic
// fixed-order combine) with guaranteed-safe margin test; near-ties recompute
// in exact fp64. (R15-proven.)
// ---------------------------------------------------------------------------
__global__ __launch_bounds__(256) void post_gemm1_kernel(
    const double* __restrict__ qpart, float* __restrict__ qn,
    const float* __restrict__ z, int* __restrict__ adec)
{
    if (blockIdx.x < 64) {
        int q = blockIdx.x * 256 + threadIdx.x;
        double s = 0.0;
        #pragma unroll
        for (int t = 0; t < 8; t++) s += qpart[(size_t)q * 8 + t];
        qn[q] = (float)s;
        return;
    }
    int b = blockIdx.x - 64;      // 0..511
    int c = b >> 2;               // class
    int wid = threadIdx.x >> 5;
    int lane = threadIdx.x & 31;
    int s = (b & 3) * 8 + wid;    // support 0..31
    const unsigned fmm = 0xffffffffu;

    const float* zs = z + (size_t)c * N_SUPPORT * Z_DIM;
    const float* zr = zs + (size_t)s * Z_DIM;

    float f0a = 0.f, f0b = 0.f, f0c = 0.f, f0d = 0.f;
    float f1a = 0.f, f1b = 0.f, f1c = 0.f, f1d = 0.f;
    #pragma unroll
    for (int i = 0; i < 8; i++) {
        int d = (i * 32 + lane) * 4;
        float4 v  = *(const float4*)(zr + d);
        float4 i0 = *(const float4*)(zs + d);
        float4 i1 = *(const float4*)(zs + Z_DIM + d);
        float ax = v.x - i0.x, ay = v.y - i0.y;
        float az = v.z - i0.z, aw = v.w - i0.w;
        f0a = fmaf(ax, ax, f0a);
        f0b = fmaf(ay, ay, f0b);
        f0c = fmaf(az, az, f0c);
        f0d = fmaf(aw, aw, f0d);
        float bx = v.x - i1.x, by = v.y - i1.y;
        float bz = v.z - i1.z, bw = v.w - i1.w;
        f1a = fmaf(bx, bx, f1a);
        f1b = fmaf(by, by, f1b);
        f1c = fmaf(bz, bz, f1c);
        f1d = fmaf(bw, bw, f1d);
    }
    float f0 = (f0a + f0b) + (f0c + f0d);
    float f1 = (f1a + f1b) + (f1c + f1d);
    #pragma unroll
    for (int o = 16; o > 0; o >>= 1) {
        f0 += __shfl_down_sync(fmm, f0, o);
        f1 += __shfl_down_sync(fmm, f1, o);
    }
    f0 = __shfl_sync(fmm, f0, 0);
    f1 = __shfl_sync(fmm, f1, 0);

    float margin = f1 - f0;
    if (fabsf(margin) >= 4.0f) {
        if (lane == 0) adec[c * N_SUPPORT + s] = (margin < 0.0f) ? 1 : 0;
        return;
    }

    double d0 = 0.0, d1 = 0.0;
    for (int d = lane; d < Z_DIM; d += 32) {
        double v = (double)zr[d];
        double a = v - (double)zs[d];
        double bb = v - (double)zs[(size_t)Z_DIM + d];
        d0 = fma(a, a, d0);
        d1 = fma(bb, bb, d1);
    }
    #pragma unroll
    for (int o = 16; o > 0; o >>= 1) {
        d0 += __shfl_down_sync(fmm, d0, o);
        d1 += __shfl_down_sync(fmm, d1, o);
    }
    if (lane == 0) adec[c * N_SUPPORT + s] = (d1 < d0) ? 1 : 0;
}

// ---------------------------------------------------------------------------
// Centroid kernel (fused): fp32 sums (4 independent support-group partials,
// fixed-order combine — same precision class as the reference's fp32 einsum),
// writes proto bf16 triple splits directly + fp64 norm partials per slice.
// grid 512 = class*4 + slice.
// ---------------------------------------------------------------------------
__global__ __launch_bounds__(256) void centroid_sum_kernel(
    const float* __restrict__ z, const int* __restrict__ adec,
    __nv_bfloat16* __restrict__ p0, __nv_bfloat16* __restrict__ p1,
    __nv_bfloat16* __restrict__ p2, double* __restrict__ ppart)
{
    int c = blockIdx.x >> 2;
    int slice = blockIdx.x & 3;
    int d = slice * 256 + threadIdx.x;
    const float* zs = z + (size_t)c * N_SUPPORT * Z_DIM;

    __shared__ unsigned int sm;
    if (threadIdx.x < 32) {
        int dec = adec[c * N_SUPPORT + threadIdx.x];
        unsigned int mm = __ballot_sync(0xffffffffu, dec != 0);
        if (threadIdx.x == 0) sm = mm;
    }
    __syncthreads();
    unsigned int m = sm;
    int cnt1 = __popc(m);
    int cnt0 = N_SUPPORT - cnt1;

    // fp32 sums, 4 independent support-group partials (fixed order)
    float s0p[4] = {0.f, 0.f, 0.f, 0.f};
    float s1p[4] = {0.f, 0.f, 0.f, 0.f};
    #pragma unroll
    for (int g = 0; g < 4; g++) {
        #pragma unroll
        for (int j = 0; j < 8; j++) {
            int s = g * 8 + j;
            float v = zs[(size_t)s * Z_DIM + d];
            if ((m >> s) & 1u) s1p[g] += v; else s0p[g] += v;
        }
    }
    float s0 = (s0p[0] + s0p[1]) + (s0p[2] + s0p[3]);
    float s1 = (s1p[0] + s1p[1]) + (s1p[2] + s1p[3]);

    float c0f = (cnt0 > 0) ? (s0 / (float)(cnt0 > 1 ? cnt0 : 1)) : zs[d];
    float c1f = (cnt1 > 0) ? (s1 / (float)(cnt1 > 1 ? cnt1 : 1))
                           : zs[(size_t)Z_DIM + d];

    // write bf16 triple splits directly
    unsigned short u0, u1, u2;
    size_t o0 = (size_t)(2 * c) * Z_DIM + d;
    size_t o1 = (size_t)(2 * c + 1) * Z_DIM + d;
    split3(c0f, u0, u1, u2);
    ((unsigned short*)p0)[o0] = u0;
    ((unsigned short*)p1)[o0] = u1;
    ((unsigned short*)p2)[o0] = u2;
    split3(c1f, u0, u1, u2);
    ((unsigned short*)p0)[o1] = u0;
    ((unsigned short*)p1)[o1] = u1;
    ((unsigned short*)p2)[o1] = u2;

    // fp64 norm partials (block tree, fixed order)
    __shared__ double r0s[256], r1s[256];
    r0s[threadIdx.x] = (double)c0f * (double)c0f;
    r1s[threadIdx.x] = (double)c1f * (double)c1f;
    __syncthreads();
    for (int o = 128; o > 0; o >>= 1) {
        if (threadIdx.x < o) {
            r0s[threadIdx.x] += r0s[threadIdx.x + o];
            r1s[threadIdx.x] += r1s[threadIdx.x + o];
        }
        __syncthreads();
    }
    if (threadIdx.x == 0) {
        ppart[(2 * c) * 4 + slice]     = r0s[0];
        ppart[(2 * c + 1) * 4 + slice] = r1s[0];
    }
}

// Tiny finalize: proto_sq[p] = fixed-order sum of 4 slice partials.
__global__ __launch_bounds__(256) void psq_finalize_kernel(
    const double* __restrict__ ppart, float* __restrict__ proto_sq)
{
    int p = threadIdx.x;
    double s = ((ppart[p * 4 + 0] + ppart[p * 4 + 1])
              + (ppart[p * 4 + 2] + ppart[p * 4 + 3]));
    proto_sq[p] = (float)s;
}

// ---------------------------------------------------------------------------
// Per-query loss + accuracy: one WARP per query, shuffle-only reductions.
// Epsilon-snapped argmax (first index on tie) identical to prior rounds.
// ---------------------------------------------------------------------------
__global__ __launch_bounds__(128) void loss_kernel(
    const float* __restrict__ dists,
    float* __restrict__ lpart, float* __restrict__ apart)
{
    const unsigned fm = 0xffffffffu;
    int w = threadIdx.x >> 5;
    int lane = threadIdx.x & 31;
    int q = blockIdx.x * 4 + w;

    float4 v = *(const float4*)(dists + (size_t)q * N_CLASS + lane * 4);

    float s = ((v.x + v.y) + (v.z + v.w));
    #pragma unroll
    for (int o = 16; o > 0; o >>= 1) s += __shfl_down_sync(fm, s, o);
    s = __shfl_sync(fm, s, 0);

    float m = fmaxf(fmaxf(v.x, v.y), fmaxf(v.z, v.w));
    #pragma unroll
    for (int o = 16; o > 0; o >>= 1) m = fmaxf(m, __shfl_down_sync(fm, m, o));
    m = __shfl_sync(fm, m, 0);

    float thresh = fmaf(m, -3e-7f, m);
    int idx = N_CLASS + 1;
    if (v.w >= thresh) idx = lane * 4 + 3;
    if (v.z >= thresh) idx = lane * 4 + 2;
    if (v.y >= thresh) idx = lane * 4 + 1;
    if (v.x >= thresh) idx = lane * 4 + 0;
    #pragma unroll
    for (int o = 16; o > 0; o >>= 1) idx = min(idx, __shfl_down_sync(fm, idx, o));

    if (lane == 0) {
        int ct = q >> 7;
        float vt = dists[(size_t)q * N_CLASS + ct];
        lpart[q] = logf(s) - logf(vt);
        apart[q] = (idx == ct) ? 1.0f : 0.0f;
    }
}

// ---------------------------------------------------------------------------
// Deterministic final reduction (fp64).
// ---------------------------------------------------------------------------
__global__ __launch_bounds__(256) void final_kernel(
    const float* __restrict__ lpart, const float* __restrict__ apart,
    float* __restrict__ out)
{
    __shared__ double ls[256], as_[256];
    int tid = threadIdx.x;
    double l = 0.0, a = 0.0;
    int base = tid * (NQ_ROWS / 256);
    for (int i = 0; i < NQ_ROWS / 256; i++) {
        l += (double)lpart[base + i];
        a += (double)apart[base + i];
    }
    ls[tid] = l; as_[tid] = a;
    __syncthreads();
    for (int o = 128; o > 0; o >>= 1) {
        if (tid < o) { ls[tid] += ls[tid + o]; as_[tid] += as_[tid + o]; }
        __syncthreads();
    }
    if (tid == 0) {
        out[0] = (float)(ls[0] / (double)NQ_ROWS);
        out[1] = (float)(as_[0] / (double)NQ_ROWS);
    }
}

// ---------------------------------------------------------------------------
// Launch
// ---------------------------------------------------------------------------
extern "C" void kernel_launch(void* const* d_in, const int* in_sizes, int n_in,
                              void* d_out, int out_size)
{
    const float* xs = (const float*)d_in[0];
    const float* xq = (const float*)d_in[1];
    const float* W  = (const float*)d_in[2];
    float* out = (float*)d_out;

    float* z;        cudaGetSymbolAddress((void**)&z, g_z);
    float* proto_sq; cudaGetSymbolAddress((void**)&proto_sq, g_proto_sq);
    double* ppart;   cudaGetSymbolAddress((void**)&ppart, g_ppart);
    float* qnorm;    cudaGetSymbolAddress((void**)&qnorm, g_qnorm);
    double* qpart;   cudaGetSymbolAddress((void**)&qpart, g_qpart);
    float* dists;    cudaGetSymbolAddress((void**)&dists, g_dists);
    float* lpart;    cudaGetSymbolAddress((void**)&lpart, g_lpart);
    float* apart;    cudaGetSymbolAddress((void**)&apart, g_apart);
    int* adec;       cudaGetSymbolAddress((void**)&adec, g_adec);
    __nv_bfloat16 *A0, *A1, *A2, *WT0, *WT1, *WT2;
    __nv_bfloat16 *Zq0, *Zq1, *Zq2, *P0, *P1, *P2;
    cudaGetSymbolAddress((void**)&A0, g_A0);
    cudaGetSymbolAddress((void**)&A1, g_A1);
    cudaGetSymbolAddress((void**)&A2, g_A2);
    cudaGetSymbolAddress((void**)&WT0, g_WT0);
    cudaGetSymbolAddress((void**)&WT1, g_WT1);
    cudaGetSymbolAddress((void**)&WT2, g_WT2);
    cudaGetSymbolAddress((void**)&Zq0, g_Zq0);
    cudaGetSymbolAddress((void**)&Zq1, g_Zq1);
    cudaGetSymbolAddress((void**)&Zq2, g_Zq2);
    cudaGetSymbolAddress((void**)&P0, g_P0);
    cudaGetSymbolAddress((void**)&P1, g_P1);
    cudaGetSymbolAddress((void**)&P2, g_P2);

    cudaFuncSetAttribute(gemm6_kernel<IN_DIM, 2>,
                         cudaFuncAttributeMaxDynamicSharedMemorySize, GT_SMEM);
    cudaFuncSetAttribute(gemm6_kernel<Z_DIM, 1>,
                         cudaFuncAttributeMaxDynamicSharedMemorySize, GT_SMEM);

    // 1) Split inputs into bf16 triples (merged xs+xq launch, 8 elems/thread)
    split_ab_kernel<<<(NZ_ROWS * IN_DIM) / 8 / 256, 256>>>(xs, xq, A0, A1, A2);
    split_wt_kernel<<<dim3(Z_DIM / 32, IN_DIM / 32), 256>>>(W, WT0, WT1, WT2);

    // 2) Projection GEMM with fused query-row split + partial norms
    gemm6_kernel<IN_DIM, 2><<<dim3(Z_DIM / 128, NZ_ROWS / 128), 256, GT_SMEM>>>(
        A0, A1, A2, WT0, WT1, WT2, z, nullptr, nullptr,
        Zq0, Zq1, Zq2, qpart);

    // 3) fused qnorm finalize + assignment; fused centroid (fp32 sums) +
    //    proto split + norm partials; tiny proto_sq finalize
    post_gemm1_kernel<<<64 + N_CLASS * 4, 256>>>(qpart, qnorm, z, adec);
    centroid_sum_kernel<<<N_CLASS * 4, 256>>>(z, adec, P0, P1, P2, ppart);
    psq_finalize_kernel<<<1, N_PROTO>>>(ppart, proto_sq);

    // 4) Query-proto distances
    gemm6_kernel<Z_DIM, 1><<<dim3(N_PROTO / 128, NQ_ROWS / 128), 256, GT_SMEM>>>(
        Zq0, Zq1, Zq2, P0, P1, P2, dists, qnorm, proto_sq,
        nullptr, nullptr, nullptr, nullptr);

    // 5) Loss / acc (warp-per-query)
    loss_kernel<<<NQ_ROWS / 4, 128>>>(dists, lpart, apart);
    final_kernel<<<1, 256>>>(lpart, apart, out);
}